// round 1
// baseline (speedup 1.0000x reference)
#include <cuda_runtime.h>
#include <math.h>

// Padded packed-cell image: for each batch, a 260x260 grid of float4 cells.
// g_pack[b][yy][xx] with yy = y0+2, xx = x0+2 holds
//   (m[y0][x0], m[y0][x0+1], m[y0+1][x0], m[y0+1][x0+1])
// where m is the circle-masked image, 0 outside [0,256)^2.
// Valid for x0,y0 in [-2, 257].
#define PACK_W 260
#define PACK_SZ (PACK_W * PACK_W)
__device__ float4 g_pack[4 * PACK_SZ];

__global__ __launch_bounds__(256) void pack_kernel(const float* __restrict__ x) {
    int idx = blockIdx.x * blockDim.x + threadIdx.x;
    if (idx >= 4 * PACK_SZ) return;
    int b  = idx / PACK_SZ;
    int r  = idx - b * PACK_SZ;
    int yy = r / PACK_W;
    int xx = r - yy * PACK_W;
    int y0 = yy - 2;
    int x0 = xx - 2;

    const float* img = x + b * 256 * 256;

    auto get = [&](int yi, int xi) -> float {
        if ((unsigned)yi > 255u || (unsigned)xi > 255u) return 0.0f;
        int dx = xi - 128, dy = yi - 128;
        if (dx * dx + dy * dy > 16384) return 0.0f;  // dist > 128 -> masked
        return img[yi * 256 + xi];
    };

    float4 q;
    q.x = get(y0,     x0);
    q.y = get(y0,     x0 + 1);
    q.z = get(y0 + 1, x0);
    q.w = get(y0 + 1, x0 + 1);
    g_pack[idx] = q;
}

// One warp per ray (b, a, j). Lanes stride over i within the in-circle range.
__global__ __launch_bounds__(256) void radon_kernel(float* __restrict__ out) {
    const int a = blockIdx.y;          // angle 0..179
    const int b = blockIdx.z;          // batch 0..3
    const int warp = threadIdx.x >> 5;
    const int lane = threadIdx.x & 31;
    const int j = blockIdx.x * 8 + warp;   // gridDim.x = 32 -> j in [0,256)

    // angle = a * pi / 179  (linspace(0,180,180) deg -> rad)
    float ang = (float)a * (float)(M_PI / 179.0);
    float s, c;
    sincosf(ang, &s, &c);

    const float v = (float)j - 127.5f;

    // Circle skip: samples with u^2+v^2 > R^2 contribute exactly 0
    // (all 4 corners are masked: R = 129.45 > 128 + sqrt(2)).
    const float RR = 129.45f * 129.45f;
    float umax = sqrtf(fmaxf(RR - v * v, 0.0f));
    int ilo = max(0,   (int)ceilf (127.5f - umax));
    int ihi = min(255, (int)floorf(127.5f + umax));

    // px = c*(i-127.5) - s*v + 127.5 ; py = s*(i-127.5) + c*v + 127.5
    const float px0 = fmaf(-127.5f, c, fmaf(-s, v, 127.5f));
    const float py0 = fmaf(-127.5f, s, fmaf( c, v, 127.5f));

    const float4* __restrict__ pk = g_pack + b * PACK_SZ;

    float acc = 0.0f;
    for (int i = ilo + lane; i <= ihi; i += 32) {
        float fi = (float)i;
        float px = fmaf(fi, c, px0);
        float py = fmaf(fi, s, py0);
        float fx = floorf(px);
        float fy = floorf(py);
        float wx = px - fx;
        float wy = py - fy;
        int x0 = (int)fx;
        int y0 = (int)fy;
        // indices guaranteed in [0, 259] by the circle bound
        float4 q = __ldg(&pk[(y0 + 2) * PACK_W + (x0 + 2)]);
        float top = fmaf(wx, q.y - q.x, q.x);
        float bot = fmaf(wx, q.w - q.z, q.z);
        acc += fmaf(wy, bot - top, top);
    }

    // warp reduction
    #pragma unroll
    for (int o = 16; o > 0; o >>= 1)
        acc += __shfl_down_sync(0xFFFFFFFFu, acc, o);

    if (lane == 0)
        out[(b * 180 + a) * 256 + j] = acc;
}

extern "C" void kernel_launch(void* const* d_in, const int* in_sizes, int n_in,
                              void* d_out, int out_size) {
    const float* x = (const float*)d_in[0];
    float* out = (float*)d_out;

    int pack_threads = 4 * PACK_SZ;
    pack_kernel<<<(pack_threads + 255) / 256, 256>>>(x);

    dim3 grid(32, 180, 4);   // 32 j-tiles x 8 warps = 256 rays per angle
    radon_kernel<<<grid, 256>>>(out);
}

// round 2
// speedup vs baseline: 1.1590x; 1.1590x over previous
#include <cuda_runtime.h>
#include <math.h>

// Padded packed-cell images, one per batch, normal + transposed orientation.
// g_pack[b][yy][xx] (yy=y0+2, xx=x0+2) = (m[y0][x0], m[y0][x0+1], m[y0+1][x0], m[y0+1][x0+1])
// g_packT is the same built on the transposed masked image.
#define PACK_W 260
#define PACK_SZ (PACK_W * PACK_W)
__device__ float4 g_pack [4 * PACK_SZ];
__device__ float4 g_packT[4 * PACK_SZ];

__global__ __launch_bounds__(256) void pack_kernel(const float* __restrict__ x) {
    int idx = blockIdx.x * blockDim.x + threadIdx.x;
    if (idx >= 4 * PACK_SZ) return;
    int b  = idx / PACK_SZ;
    int r  = idx - b * PACK_SZ;
    int yy = r / PACK_W;
    int xx = r - yy * PACK_W;
    int y0 = yy - 2;
    int x0 = xx - 2;

    const float* img = x + b * 256 * 256;

    auto get = [&](int yi, int xi) -> float {
        if ((unsigned)yi > 255u || (unsigned)xi > 255u) return 0.0f;
        int dx = xi - 128, dy = yi - 128;
        if (dx * dx + dy * dy > 16384) return 0.0f;  // circle mask, center 128, R 128
        return img[yi * 256 + xi];
    };

    float4 q;
    q.x = get(y0,     x0);
    q.y = get(y0,     x0 + 1);
    q.z = get(y0 + 1, x0);
    q.w = get(y0 + 1, x0 + 1);
    g_pack[idx] = q;

    // transposed image cell at same (yy, xx): imgT[r][c] = img[c][r]
    float4 t;
    t.x = get(x0,     y0);
    t.y = get(x0 + 1, y0);
    t.z = get(x0,     y0 + 1);
    t.w = get(x0 + 1, y0 + 1);
    g_packT[idx] = t;
}

// One warp per ray (a, j); all 4 batches processed in the same lane.
__global__ __launch_bounds__(256) void radon_kernel(float* __restrict__ out) {
    const int a = blockIdx.y;              // angle 0..179
    const int warp = threadIdx.x >> 5;
    const int lane = threadIdx.x & 31;
    const int j = blockIdx.x * 8 + warp;   // gridDim.x = 32 -> j in [0,256)

    float ang = (float)a * (float)(M_PI / 179.0);
    float s, c;
    sincosf(ang, &s, &c);

    const float v = (float)j - 127.5f;

    // Circle skip (R=129.45 proven sufficient: max contributing radius < 128.92)
    const float RR = 129.45f * 129.45f;
    float umax = sqrtf(fmaxf(RR - v * v, 0.0f));
    int ilo = max(0,   (int)ceilf (127.5f - umax));
    int ihi = min(255, (int)floorf(127.5f + umax));

    // Orientation choice: walk slope = se/ce with |se| = min(|s|,|c|)
    const bool swp = fabsf(s) > fabsf(c);
    float ce, se, px0, py0;
    if (!swp) {
        ce = c; se = s;
        px0 = fmaf(-127.5f, c, fmaf(-s, v, 127.5f));
        py0 = fmaf(-127.5f, s, fmaf( c, v, 127.5f));
    } else {
        // bilerp(img, px, py) == bilerp(imgT, py, px)
        ce = s; se = c;
        px0 = fmaf(-127.5f, s, fmaf( c, v, 127.5f));
        py0 = fmaf(-127.5f, c, fmaf(-s, v, 127.5f));
    }
    const float4* __restrict__ pk = (swp ? g_packT : g_pack) + 522;  // (+2,+2) fold

    float acc0 = 0.f, acc1 = 0.f, acc2 = 0.f, acc3 = 0.f;

    float fi = (float)(ilo + lane);
    for (int n = ihi - (ilo + lane); n >= 0; n -= 32, fi += 32.0f) {
        float px = fmaf(fi, ce, px0);
        float py = fmaf(fi, se, py0);
        float fx = floorf(px);
        float fy = floorf(py);
        float wx = px - fx;
        float wy = py - fy;
        int x0 = (int)fx;
        int y0 = (int)fy;
        int idx = y0 * PACK_W + x0;       // in [-522+..., ...] valid after +522 fold

        float4 q0 = __ldg(&pk[idx]);
        float4 q1 = __ldg(&pk[idx + PACK_SZ]);
        float4 q2 = __ldg(&pk[idx + 2 * PACK_SZ]);
        float4 q3 = __ldg(&pk[idx + 3 * PACK_SZ]);

        {
            float top = fmaf(wx, q0.y - q0.x, q0.x);
            float bot = fmaf(wx, q0.w - q0.z, q0.z);
            acc0 += fmaf(wy, bot - top, top);
        }
        {
            float top = fmaf(wx, q1.y - q1.x, q1.x);
            float bot = fmaf(wx, q1.w - q1.z, q1.z);
            acc1 += fmaf(wy, bot - top, top);
        }
        {
            float top = fmaf(wx, q2.y - q2.x, q2.x);
            float bot = fmaf(wx, q2.w - q2.z, q2.z);
            acc2 += fmaf(wy, bot - top, top);
        }
        {
            float top = fmaf(wx, q3.y - q3.x, q3.x);
            float bot = fmaf(wx, q3.w - q3.z, q3.z);
            acc3 += fmaf(wy, bot - top, top);
        }
    }

    #pragma unroll
    for (int o = 16; o > 0; o >>= 1) {
        acc0 += __shfl_down_sync(0xFFFFFFFFu, acc0, o);
        acc1 += __shfl_down_sync(0xFFFFFFFFu, acc1, o);
        acc2 += __shfl_down_sync(0xFFFFFFFFu, acc2, o);
        acc3 += __shfl_down_sync(0xFFFFFFFFu, acc3, o);
    }

    if (lane == 0) {
        out[(0 * 180 + a) * 256 + j] = acc0;
        out[(1 * 180 + a) * 256 + j] = acc1;
        out[(2 * 180 + a) * 256 + j] = acc2;
        out[(3 * 180 + a) * 256 + j] = acc3;
    }
}

extern "C" void kernel_launch(void* const* d_in, const int* in_sizes, int n_in,
                              void* d_out, int out_size) {
    const float* x = (const float*)d_in[0];
    float* out = (float*)d_out;

    int pack_threads = 4 * PACK_SZ;
    pack_kernel<<<(pack_threads + 255) / 256, 256>>>(x);

    dim3 grid(32, 180, 1);   // 32 j-tiles x 8 warps = 256 rays per angle, all batches fused
    radon_kernel<<<grid, 256>>>(out);
}